// round 2
// baseline (speedup 1.0000x reference)
#include <cuda_runtime.h>
#include <math.h>

#define M_TOTAL 184320
#define IMG 256
#define ORTHO_F (1.0f/256.0f)

typedef unsigned long long u64;

// scratch for k-space data-consistency result (complex), static device alloc
__device__ float2 g_kdc[M_TOTAL];

__device__ __forceinline__ float2 cmulf(float2 a, float2 b){
    return make_float2(a.x*b.x - a.y*b.y, a.x*b.y + a.y*b.x);
}
__device__ __forceinline__ float2 conjf2(float2 a){ return make_float2(a.x, -a.y); }

// w^n for integer n (may be negative), |n| <= 256.
__device__ __forceinline__ float2 cpow_int(float2 w, int n){
    if (n < 0){ w = conjf2(w); n = -n; }
    float2 r = make_float2(1.f, 0.f);
    float2 t = w;
    while (n){
        if (n & 1) r = cmulf(r, t);
        t = cmulf(t, t);
        n >>= 1;
    }
    return r;
}

// ---- packed f32x2 helpers --------------------------------------------------
__device__ __forceinline__ u64 pack2(float lo, float hi){
    u64 r; asm("mov.b64 %0, {%1, %2};" : "=l"(r) : "f"(lo), "f"(hi)); return r;
}
__device__ __forceinline__ float2 unpack2(u64 v){
    float2 r; asm("mov.b64 {%0, %1}, %2;" : "=f"(r.x), "=f"(r.y) : "l"(v)); return r;
}
// acc = a*b + acc, lanewise on packed fp32 pairs (FFMA2 — 2x fp32 throughput)
#define FMA2(acc, a2, b2) \
    asm("fma.rn.f32x2 %0, %1, %2, %0;" : "+l"(acc) : "l"(a2), "l"(b2))

// ============================================================================
// Forward: A[m] = ORTHO * sum_{u,w} img[u,w] e^{-i kx_m (u-128)} e^{-i ky_m (w-128)}
// GEMM over u:  C[m,w] = sum_u Ex[m,u] * img[u,w], epilogue reduce over w w/ Ey,
// then DC blend -> g_kdc[m].
// Block: 32 m, full 256 w. 8 warps: warp owns 4 m; lane + 32*j covers w.
// Complex MAC via 2x fma.rn.f32x2 (re,im packed per accumulator).
// ============================================================================
__global__ __launch_bounds__(256) void fwd_kernel(
    const float* __restrict__ img,      // (256,256,2)
    const float* __restrict__ y_radial, // (640,288,2)
    const float* __restrict__ lambda_p, // (1,)
    const float* __restrict__ ktraj)    // kx[M] then ky[M]
{
    __shared__ float2 smA[8][32];       // Ex tile [k][m]
    __shared__ float4 smB4[8][128];     // img rows [k][w-pairs]

    const int tid  = threadIdx.x;
    const int lane = tid & 31;
    const int warp = tid >> 5;
    const int m_base = blockIdx.x * 32;

    u64 acc[4][8];
    #pragma unroll
    for (int i = 0; i < 4; i++)
        #pragma unroll
        for (int j = 0; j < 8; j++) acc[i][j] = 0ull;

    // warp 0 lane l owns recurrence for m-row l
    float2 cur = make_float2(1.f, 0.f);
    float2 wx  = make_float2(1.f, 0.f);
    if (warp == 0){
        float kx = ktraj[m_base + lane];
        float s, c; sincosf(kx, &s, &c);
        wx  = make_float2(c, -s);          // e^{-i kx}
        cur = cpow_int(wx, -128);
    }

    for (int u0 = 0; u0 < 256; u0 += 8){
        __syncthreads();
        if (warp == 0){
            #pragma unroll
            for (int k = 0; k < 8; k++){
                smA[k][lane] = cur;
                cur = cmulf(cur, wx);
            }
        }
        const float4* gB = (const float4*)(img + (size_t)u0 * IMG * 2);
        #pragma unroll
        for (int p = 0; p < 4; p++){
            int idx = p * 256 + tid;
            ((float4*)smB4)[idx] = gB[idx];
        }
        __syncthreads();

        const float2* smB = (const float2*)smB4;
        #pragma unroll
        for (int k = 0; k < 8; k++){
            float4 a01 = *((const float4*)&smA[k][warp*4]);
            float4 a23 = *((const float4*)&smA[k][warp*4 + 2]);
            u64 axx[4], ayn[4];
            axx[0] = pack2(a01.x, a01.x);  ayn[0] = pack2(-a01.y, a01.y);
            axx[1] = pack2(a01.z, a01.z);  ayn[1] = pack2(-a01.w, a01.w);
            axx[2] = pack2(a23.x, a23.x);  ayn[2] = pack2(-a23.y, a23.y);
            axx[3] = pack2(a23.z, a23.z);  ayn[3] = pack2(-a23.w, a23.w);
            #pragma unroll
            for (int j = 0; j < 8; j++){
                float2 b = smB[k*256 + lane + 32*j];
                u64 bn = pack2(b.x, b.y);
                u64 bs = pack2(b.y, b.x);
                #pragma unroll
                for (int i = 0; i < 4; i++){
                    FMA2(acc[i][j], axx[i], bn);
                    FMA2(acc[i][j], ayn[i], bs);
                }
            }
        }
    }

    // Epilogue: A_m = sum_w Ey[m,w] * C[m,w], blend.
    float lam = 1.f / (1.f + expf(-lambda_p[0]));

    #pragma unroll
    for (int i = 0; i < 4; i++){
        int m = m_base + warp*4 + i;
        float ky = ktraj[M_TOTAL + m];
        float s, c; sincosf(ky, &s, &c);
        float2 wy = make_float2(c, -s);    // e^{-i ky}

        float2 t = wy, r = make_float2(1.f, 0.f);
        int e_ = lane;
        #pragma unroll
        for (int b = 0; b < 5; b++){
            if (e_ & 1) r = cmulf(r, t);
            t = cmulf(t, t);
            e_ >>= 1;
        }
        float2 w32  = t;
        float2 w64  = cmulf(t, t);
        float2 w128 = cmulf(w64, w64);
        float2 e    = cmulf(r, conjf2(w128));  // wy^{lane-128}

        float2 part = make_float2(0.f, 0.f);
        #pragma unroll
        for (int j = 0; j < 8; j++){
            float2 av = unpack2(acc[i][j]);
            part.x += e.x*av.x - e.y*av.y;
            part.y += e.x*av.y + e.y*av.x;
            e = cmulf(e, w32);
        }
        #pragma unroll
        for (int off = 16; off > 0; off >>= 1){
            part.x += __shfl_xor_sync(0xffffffffu, part.x, off);
            part.y += __shfl_xor_sync(0xffffffffu, part.y, off);
        }
        if (lane == 0){
            float kx  = ktraj[m];
            float dcf = sqrtf(kx*kx + ky*ky);
            float a_re = part.x * ORTHO_F;
            float a_im = part.y * ORTHO_F;
            int tt = m % 640;
            int ss = m / 640;
            const float* yp = y_radial + ((size_t)tt*288 + ss)*2;
            float2 kd;
            kd.x = lam*dcf*a_re + (1.f - lam)*yp[0];
            kd.y = lam*dcf*a_im + (1.f - lam)*yp[1];
            g_kdc[m] = kd;
        }
    }
}

// ============================================================================
// Adjoint: x[u,v] = ORTHO * sum_m k_m e^{+i kx_m (u-128)} e^{+i ky_m (v-128)}
// Split-K GEMM, 64x64 output tile, operands generated in smem per K-slab.
// ============================================================================
#define CHUNK 1536
#define BKA   16
#define PADR  66

__global__ __launch_bounds__(256) void adj_kernel(
    const float* __restrict__ ktraj,
    float* __restrict__ out)
{
    __shared__ float2 smA[BKA][PADR];
    __shared__ float2 smB[BKA][PADR];

    const int tid  = threadIdx.x;
    const int lane = tid & 31;
    const int warp = tid >> 5;
    const int tx = tid & 15;
    const int ty = tid >> 4;
    const int u_base = blockIdx.y * 64;
    const int v_base = blockIdx.x * 64;
    const int m0 = blockIdx.z * CHUNK;

    u64 acc[4][4];
    #pragma unroll
    for (int i = 0; i < 4; i++)
        #pragma unroll
        for (int j = 0; j < 4; j++) acc[i][j] = 0ull;

    for (int step = 0; step < CHUNK/BKA; ++step){
        __syncthreads();
        if (warp == 0 && lane < 16){
            int m = m0 + step*BKA + lane;
            float kx = ktraj[m];
            float s, c; sincosf(kx, &s, &c);
            float2 w = make_float2(c, s);          // e^{+i kx}
            float2 e = cpow_int(w, u_base - 128);
            #pragma unroll
            for (int i = 0; i < 64; i++){
                smA[lane][i] = e;
                e = cmulf(e, w);
            }
        } else if (warp == 1 && lane < 16){
            int m = m0 + step*BKA + lane;
            float ky = ktraj[M_TOTAL + m];
            float s, c; sincosf(ky, &s, &c);
            float2 w = make_float2(c, s);          // e^{+i ky}
            float2 e = cpow_int(w, v_base - 128);
            float2 km = g_kdc[m];
            km.x *= ORTHO_F; km.y *= ORTHO_F;
            #pragma unroll
            for (int i = 0; i < 64; i++){
                smB[lane][i] = cmulf(km, e);
                e = cmulf(e, w);
            }
        }
        __syncthreads();

        #pragma unroll
        for (int k = 0; k < BKA; k++){
            float4 a01 = *((const float4*)&smA[k][ty*4]);
            float4 a23 = *((const float4*)&smA[k][ty*4 + 2]);
            u64 axx[4], ayn[4];
            axx[0] = pack2(a01.x, a01.x);  ayn[0] = pack2(-a01.y, a01.y);
            axx[1] = pack2(a01.z, a01.z);  ayn[1] = pack2(-a01.w, a01.w);
            axx[2] = pack2(a23.x, a23.x);  ayn[2] = pack2(-a23.y, a23.y);
            axx[3] = pack2(a23.z, a23.z);  ayn[3] = pack2(-a23.w, a23.w);
            #pragma unroll
            for (int j = 0; j < 4; j++){
                float2 b = smB[k][tx + 16*j];
                u64 bn = pack2(b.x, b.y);
                u64 bs = pack2(b.y, b.x);
                #pragma unroll
                for (int i = 0; i < 4; i++){
                    FMA2(acc[i][j], axx[i], bn);
                    FMA2(acc[i][j], ayn[i], bs);
                }
            }
        }
    }

    #pragma unroll
    for (int i = 0; i < 4; i++){
        int u = u_base + ty*4 + i;
        #pragma unroll
        for (int j = 0; j < 4; j++){
            int v = v_base + tx + 16*j;
            float2 av = unpack2(acc[i][j]);
            float* p = out + ((size_t)u*256 + v)*2;
            atomicAdd(p,     av.x);
            atomicAdd(p + 1, av.y);
        }
    }
}

__global__ void zero_kernel(float* out, int n){
    int i = blockIdx.x * 256 + threadIdx.x;
    if (i < n) out[i] = 0.f;
}

extern "C" void kernel_launch(void* const* d_in, const int* in_sizes, int n_in,
                              void* d_out, int out_size)
{
    const float* x   = (const float*)d_in[0];  // (1,1,256,256,2)
    const float* y   = (const float*)d_in[1];  // (640,288,2)
    const float* lp  = (const float*)d_in[2];  // (1,)
    const float* kt  = (const float*)d_in[3];  // (1,2,184320)
    float* out = (float*)d_out;                // (1,1,256,256,2)

    zero_kernel<<<(out_size + 255)/256, 256>>>(out, out_size);
    fwd_kernel<<<M_TOTAL/32, 256>>>(x, y, lp, kt);
    adj_kernel<<<dim3(4, 4, M_TOTAL/CHUNK), 256>>>(kt, out);
}

// round 3
// speedup vs baseline: 2.2812x; 2.2812x over previous
#include <cuda_runtime.h>
#include <cuda_bf16.h>
#include <math.h>

#define M_TOTAL 184320
#define ORTHO_F (1.0f/256.0f)

typedef unsigned int u32;

// k-space data-consistency scratch (complex)
__device__ float2 g_kdc[M_TOTAL];

__device__ __forceinline__ float2 cmulf(float2 a, float2 b){
    return make_float2(fmaf(a.x, b.x, -(a.y*b.y)), fmaf(a.x, b.y, a.y*b.x));
}

// split fp32 -> bf16 hi + bf16 lo (16-bit payloads in low halves)
__device__ __forceinline__ void splitf(float x, u32 &hb, u32 &lb){
    unsigned short h = __bfloat16_as_ushort(__float2bfloat16(x));
    float hf = __uint_as_float(((u32)h) << 16);
    unsigned short l = __bfloat16_as_ushort(__float2bfloat16(x - hf));
    hb = (u32)h; lb = (u32)l;
}

#define MMA(c, a0,a1,a2,a3, b0,b1) \
    asm volatile("mma.sync.aligned.m16n8k16.row.col.f32.bf16.bf16.f32 " \
        "{%0,%1,%2,%3}, {%4,%5,%6,%7}, {%8,%9}, {%0,%1,%2,%3};" \
        : "+f"((c)[0]), "+f"((c)[1]), "+f"((c)[2]), "+f"((c)[3]) \
        : "r"(a0), "r"(a1), "r"(a2), "r"(a3), "r"(b0), "r"(b1))

#define AST 12    // A smem row stride (u32) -> conflict-free frag loads
#define BST 520   // B smem row stride (u32) -> bank = g + 8*tig, all distinct

// ============================================================================
// Forward: complex GEMM C[m,w] = sum_u Ex[m,u]*img[u,w] as real GEMM
// [64m x 512n'] per block, K' = 512 (u expanded x2), split-bf16 x3 MMA.
// Epilogue: reduce over w with Ey[m,w], DC blend -> g_kdc.
// 512 threads = 16 warps: 4 m-warps x 4 n-warps.
// ============================================================================
__global__ __launch_bounds__(512, 1) void fwd_kernel(
    const float* __restrict__ img,      // (256,256,2)
    const float* __restrict__ y_radial, // (640,288,2)
    const float* __restrict__ lambda_p,
    const float* __restrict__ ktraj)    // kx[M], ky[M]
{
    __shared__ u32 sAh[64*AST], sAl[64*AST];
    __shared__ u32 sBh[8*BST],  sBl[8*BST];
    __shared__ float2 sEpi[64][4];

    const int tid  = threadIdx.x;
    const int lane = tid & 31;
    const int warp = tid >> 5;
    const int mw = warp >> 2, nw = warp & 3;
    const int g = lane >> 2, tig = lane & 3;
    const int mbase = blockIdx.x * 64;

    float acc[16][4];
    #pragma unroll
    for (int nt = 0; nt < 16; nt++)
        #pragma unroll
        for (int c = 0; c < 4; c++) acc[nt][c] = 0.f;

    // per-m recurrence constants (thread tid<64 owns m row tid)
    float kxA = 0.f; float2 wxA = make_float2(1.f, 0.f);
    if (tid < 64){
        kxA = ktraj[mbase + tid];
        float s, c; sincosf(kxA, &s, &c);
        wxA = make_float2(c, -s);               // e^{-i kx}
    }

    // prefetch B source rows for step 0
    float2 pf[4];
    #pragma unroll
    for (int p = 0; p < 4; p++){
        int idx = tid + p*512;
        pf[p] = ((const float2*)img)[ (idx >> 8)*256 + (idx & 255) ];
    }

    for (int step = 0; step < 32; ++step){
        __syncthreads();                        // previous MMA phase done

        // ---- A gen: Ex[m, u0..u0+7], reseeded by sincos each step ----
        if (tid < 64){
            float ang = kxA * (float)(128 - step*8);   // -kx*(u0-128)
            float2 cur; sincosf(ang, &cur.y, &cur.x);  // (cos, sin) = (ar, ai)
            #pragma unroll
            for (int i = 0; i < 8; i++){
                u32 xh, xl, yh, yl;
                splitf(cur.x, xh, xl); splitf(cur.y, yh, yl);
                sAh[tid*AST + i] = xh | (yh << 16);
                sAl[tid*AST + i] = xl | (yl << 16);
                cur = cmulf(cur, wxA);
            }
        }
        // ---- B gen: expanded image rows from prefetched fp32 ----
        #pragma unroll
        for (int p = 0; p < 4; p++){
            int idx = tid + p*512;
            int ul = idx >> 8, w = idx & 255;
            u32 rh, rl, ih, il;
            splitf(pf[p].x, rh, rl); splitf(pf[p].y, ih, il);
            sBh[ul*BST + 2*w    ] = rh | ((ih ^ 0x8000u) << 16);  // (xr, -xi)
            sBh[ul*BST + 2*w + 1] = ih | (rh << 16);              // (xi,  xr)
            sBl[ul*BST + 2*w    ] = rl | ((il ^ 0x8000u) << 16);
            sBl[ul*BST + 2*w + 1] = il | (rl << 16);
        }
        // prefetch next step's source
        if (step < 31){
            #pragma unroll
            for (int p = 0; p < 4; p++){
                int idx = tid + p*512;
                pf[p] = ((const float2*)img)[ ((step+1)*8 + (idx >> 8))*256 + (idx & 255) ];
            }
        }
        __syncthreads();

        // ---- MMA phase ----
        const int m0 = mw*16;
        u32 ah0 = sAh[(m0+g  )*AST + tig],   ah1 = sAh[(m0+g+8)*AST + tig];
        u32 ah2 = sAh[(m0+g  )*AST + tig+4], ah3 = sAh[(m0+g+8)*AST + tig+4];
        u32 al0 = sAl[(m0+g  )*AST + tig],   al1 = sAl[(m0+g+8)*AST + tig];
        u32 al2 = sAl[(m0+g  )*AST + tig+4], al3 = sAl[(m0+g+8)*AST + tig+4];
        #pragma unroll
        for (int nt = 0; nt < 16; nt++){
            int col = nw*128 + nt*8 + g;
            u32 bh0 = sBh[ tig   *BST + col], bh1 = sBh[(tig+4)*BST + col];
            u32 bl0 = sBl[ tig   *BST + col], bl1 = sBl[(tig+4)*BST + col];
            MMA(acc[nt], ah0, ah1, ah2, ah3, bh0, bh1);
            MMA(acc[nt], ah0, ah1, ah2, ah3, bl0, bl1);
            MMA(acc[nt], al0, al1, al2, al3, bh0, bh1);
        }
    }

    // ---- Epilogue: A_m = ORTHO * sum_w C[m,w]*Ey[m,w], blend ----
    float lam = 1.f / (1.f + expf(-lambda_p[0]));

    #pragma unroll
    for (int r = 0; r < 2; r++){
        int ml = mw*16 + g + 8*r;
        int m  = mbase + ml;
        float ky = ktraj[M_TOTAL + m];
        int w0 = nw*64 + tig;
        float2 e, st;
        { float s, c; sincosf(-ky * (float)(w0 - 128), &s, &c); e  = make_float2(c, s); }
        { float s, c; sincosf(-4.f * ky,               &s, &c); st = make_float2(c, s); }
        float2 part = make_float2(0.f, 0.f);
        #pragma unroll
        for (int nt = 0; nt < 16; nt++){
            float cr = acc[nt][2*r], ci = acc[nt][2*r + 1];
            part.x += cr*e.x - ci*e.y;
            part.y += cr*e.y + ci*e.x;
            e = cmulf(e, st);                  // advance w by 4
        }
        part.x += __shfl_xor_sync(0xffffffffu, part.x, 1);
        part.y += __shfl_xor_sync(0xffffffffu, part.y, 1);
        part.x += __shfl_xor_sync(0xffffffffu, part.x, 2);
        part.y += __shfl_xor_sync(0xffffffffu, part.y, 2);
        if (tig == 0) sEpi[ml][nw] = part;
    }
    __syncthreads();

    if (tid < 64){
        float2 s = sEpi[tid][0];
        s.x += sEpi[tid][1].x + sEpi[tid][2].x + sEpi[tid][3].x;
        s.y += sEpi[tid][1].y + sEpi[tid][2].y + sEpi[tid][3].y;
        int m = mbase + tid;
        float kx = ktraj[m], ky = ktraj[M_TOTAL + m];
        float dcf = sqrtf(kx*kx + ky*ky);
        float ar = s.x * ORTHO_F, ai = s.y * ORTHO_F;
        int tt = m % 640, ss = m / 640;
        const float* yp = y_radial + ((size_t)tt*288 + ss)*2;
        float2 kd;
        kd.x = lam*dcf*ar + (1.f - lam)*yp[0];
        kd.y = lam*dcf*ai + (1.f - lam)*yp[1];
        g_kdc[m] = kd;
    }
}

// ============================================================================
// Adjoint: X[u,v] = ORTHO * sum_m kdc_m e^{+i kx_m u_c} e^{+i ky_m v_c}
// Real GEMM [64u x 512n'] per block, K' = 2*chunk, split-K over blockIdx.x.
// ============================================================================
#define ADJ_Z  72
#define ADJ_MS 2560   // m per chunk (72*2560 = 184320)

__global__ __launch_bounds__(512, 1) void adj_kernel(
    const float* __restrict__ ktraj,
    float* __restrict__ out)
{
    __shared__ u32 sAh[64*AST], sAl[64*AST];
    __shared__ u32 sBh[8*BST],  sBl[8*BST];

    const int tid  = threadIdx.x;
    const int lane = tid & 31;
    const int warp = tid >> 5;
    const int uw = warp >> 2, nw = warp & 3;
    const int g = lane >> 2, tig = lane & 3;
    const int ublk = blockIdx.y;
    const int m0base = blockIdx.x * ADJ_MS;

    float acc[16][4];
    #pragma unroll
    for (int nt = 0; nt < 16; nt++)
        #pragma unroll
        for (int c = 0; c < 4; c++) acc[nt][c] = 0.f;

    // gen roles
    const bool isA = (tid < 32);
    const int  aseg = tid >> 3, aml = tid & 7;
    const bool isB = (tid >= 64 && tid < 320);
    const int  bidx = tid - 64;
    const int  bml = bidx >> 5, bvs = bidx & 31;

    float kx_c = 0.f, ky_c = 0.f; float2 kd_c = make_float2(0.f, 0.f);
    if (isA) kx_c = ktraj[m0base + aml];
    if (isB){ ky_c = ktraj[M_TOTAL + m0base + bml]; kd_c = g_kdc[m0base + bml]; }

    for (int step = 0; step < ADJ_MS/8; ++step){
        __syncthreads();

        // ---- A gen: e^{+i kx u_c} for this block's 64 u, 8 m-cols ----
        if (isA){
            float u0 = (float)(ublk*64 + aseg*16 - 128);
            float2 e, w;
            { float s, c; sincosf(kx_c * u0, &s, &c); e = make_float2(c, s); }
            { float s, c; sincosf(kx_c,      &s, &c); w = make_float2(c, s); }
            #pragma unroll
            for (int i = 0; i < 16; i++){
                int u = aseg*16 + i;
                u32 xh, xl, yh, yl;
                splitf(e.x, xh, xl); splitf(e.y, yh, yl);
                sAh[u*AST + aml] = xh | (yh << 16);
                sAl[u*AST + aml] = xl | (yl << 16);
                e = cmulf(e, w);
            }
        }
        // ---- B gen: ORTHO*kdc_m*e^{+i ky v_c}, v strided by 32 per iter ----
        if (isB){
            float2 kd = make_float2(kd_c.x * ORTHO_F, kd_c.y * ORTHO_F);
            float2 b, w32;
            { float s, c; sincosf(ky_c * (float)(bvs - 128), &s, &c);
              b = cmulf(kd, make_float2(c, s)); }
            { float s, c; sincosf(32.f * ky_c, &s, &c); w32 = make_float2(c, s); }
            #pragma unroll
            for (int i = 0; i < 8; i++){
                int v = bvs + 32*i;
                u32 rh, rl, ih, il;
                splitf(b.x, rh, rl); splitf(b.y, ih, il);
                sBh[bml*BST + 2*v    ] = rh | ((ih ^ 0x8000u) << 16); // (br, -bi)
                sBh[bml*BST + 2*v + 1] = ih | (rh << 16);             // (bi,  br)
                sBl[bml*BST + 2*v    ] = rl | ((il ^ 0x8000u) << 16);
                sBl[bml*BST + 2*v + 1] = il | (rl << 16);
                b = cmulf(b, w32);
            }
        }
        // prefetch next step's per-m params
        if (step + 1 < ADJ_MS/8){
            int mn = m0base + (step + 1)*8;
            if (isA) kx_c = ktraj[mn + aml];
            if (isB){ ky_c = ktraj[M_TOTAL + mn + bml]; kd_c = g_kdc[mn + bml]; }
        }
        __syncthreads();

        // ---- MMA phase ----
        const int u0 = uw*16;
        u32 ah0 = sAh[(u0+g  )*AST + tig],   ah1 = sAh[(u0+g+8)*AST + tig];
        u32 ah2 = sAh[(u0+g  )*AST + tig+4], ah3 = sAh[(u0+g+8)*AST + tig+4];
        u32 al0 = sAl[(u0+g  )*AST + tig],   al1 = sAl[(u0+g+8)*AST + tig];
        u32 al2 = sAl[(u0+g  )*AST + tig+4], al3 = sAl[(u0+g+8)*AST + tig+4];
        #pragma unroll
        for (int nt = 0; nt < 16; nt++){
            int col = nw*128 + nt*8 + g;
            u32 bh0 = sBh[ tig   *BST + col], bh1 = sBh[(tig+4)*BST + col];
            u32 bl0 = sBl[ tig   *BST + col], bl1 = sBl[(tig+4)*BST + col];
            MMA(acc[nt], ah0, ah1, ah2, ah3, bh0, bh1);
            MMA(acc[nt], ah0, ah1, ah2, ah3, bl0, bl1);
            MMA(acc[nt], al0, al1, al2, al3, bh0, bh1);
        }
    }

    // ---- split-K accumulate: out[u*512 + n'] ----
    #pragma unroll
    for (int nt = 0; nt < 16; nt++){
        int np = nw*128 + nt*8 + 2*tig;
        int r0 = ublk*64 + uw*16 + g;
        float* p0 = out + (size_t)r0*512 + np;
        float* p1 = out + (size_t)(r0+8)*512 + np;
        atomicAdd(p0,     acc[nt][0]);
        atomicAdd(p0 + 1, acc[nt][1]);
        atomicAdd(p1,     acc[nt][2]);
        atomicAdd(p1 + 1, acc[nt][3]);
    }
}

__global__ void zero_kernel(float* out, int n){
    int i = blockIdx.x * 512 + threadIdx.x;
    if (i < n) out[i] = 0.f;
}

extern "C" void kernel_launch(void* const* d_in, const int* in_sizes, int n_in,
                              void* d_out, int out_size)
{
    const float* x   = (const float*)d_in[0];  // (1,1,256,256,2)
    const float* y   = (const float*)d_in[1];  // (640,288,2)
    const float* lp  = (const float*)d_in[2];  // (1,)
    const float* kt  = (const float*)d_in[3];  // (1,2,184320)
    float* out = (float*)d_out;                // (1,1,256,256,2)

    zero_kernel<<<(out_size + 511)/512, 512>>>(out, out_size);
    fwd_kernel<<<M_TOTAL/64, 512>>>(x, y, lp, kt);
    adj_kernel<<<dim3(ADJ_Z, 4), 512>>>(kt, out);
}

// round 4
// speedup vs baseline: 2.5849x; 1.1331x over previous
#include <cuda_runtime.h>
#include <cuda_bf16.h>
#include <math.h>

#define M_TOTAL 184320
#define ORTHO_F (1.0f/256.0f)

typedef unsigned int u32;
typedef unsigned long long u64;

// scratch (static device allocs; allowed)
__device__ float2 g_kdc[M_TOTAL];
__device__ u32 g_Bh[256*512];   // expanded image, bf16-hi, pre-transformed cols
__device__ u32 g_Bl[256*512];   // bf16-lo residual

__device__ __forceinline__ float2 cmulf(float2 a, float2 b){
    return make_float2(fmaf(a.x,b.x,-(a.y*b.y)), fmaf(a.x,b.y,a.y*b.x));
}
// pack: low16 = bf16(x), high16 = bf16(y)
__device__ __forceinline__ u32 bf2pack(float x, float y){
    u32 r; asm("cvt.rn.bf16x2.f32 %0, %1, %2;" : "=r"(r) : "f"(y), "f"(x)); return r;
}
// split complex (x,y) -> hi pair + lo residual pair
__device__ __forceinline__ void csplit(float x, float y, u32 &h32, u32 &l32){
    h32 = bf2pack(x, y);
    float hx = __uint_as_float(h32 << 16);
    float hy = __uint_as_float(h32 & 0xFFFF0000u);
    l32 = bf2pack(x - hx, y - hy);
}

#define MMA(c, a0,a1,a2,a3, b0,b1) \
    asm volatile("mma.sync.aligned.m16n8k16.row.col.f32.bf16.bf16.f32 " \
        "{%0,%1,%2,%3}, {%4,%5,%6,%7}, {%8,%9}, {%0,%1,%2,%3};" \
        : "+f"((c)[0]), "+f"((c)[1]), "+f"((c)[2]), "+f"((c)[3]) \
        : "r"(a0), "r"(a1), "r"(a2), "r"(a3), "r"(b0), "r"(b1))

__device__ __forceinline__ void cpa16(u32* dst, const u32* src){
    u32 d = (u32)__cvta_generic_to_shared(dst);
    asm volatile("cp.async.cg.shared.global [%0], [%1], 16;" :: "r"(d), "l"(src));
}
#define CP_COMMIT() asm volatile("cp.async.commit_group;")
#define CP_WAIT(n)  asm volatile("cp.async.wait_group %0;" :: "n"(n))

#define AST 12
#define BST 520
#define ABUF (64*AST)
#define BBUF (8*BST)

// ============================================================================
// Prep: expand fp32 image -> split-bf16, column-transformed B layout.
// g_B*[u][2w] = (r, -i), g_B*[u][2w+1] = (i, r)  (k'-pair (2u,2u+1) packed)
// ============================================================================
__global__ void prep_kernel(const float* __restrict__ img){
    int idx = blockIdx.x*256 + threadIdx.x;       // 0..65535
    int u = idx >> 8, w = idx & 255;
    float2 p = ((const float2*)img)[idx];
    u32 h32, l32; csplit(p.x, p.y, h32, l32);
    g_Bh[u*512 + 2*w    ] = h32 ^ 0x80000000u;
    g_Bh[u*512 + 2*w + 1] = __byte_perm(h32, h32, 0x1032);
    g_Bl[u*512 + 2*w    ] = l32 ^ 0x80000000u;
    g_Bl[u*512 + 2*w + 1] = __byte_perm(l32, l32, 0x1032);
}

// ============================================================================
// Forward: block 64 m x 512 n', 512 threads (16 warps = 4 mw x 4 nw).
// Pipelined: A triple-buffer (STS), B double-buffer (cp.async from g_B*).
// ============================================================================
__global__ __launch_bounds__(512, 1) void fwd_kernel(
    const float* __restrict__ y_radial,
    const float* __restrict__ lambda_p,
    const float* __restrict__ ktraj)
{
    extern __shared__ u32 dyn[];
    u32* sA = dyn;                     // 6*ABUF (3 bufs x hi/lo)
    u32* sB = dyn + 6*ABUF;            // 4*BBUF (2 bufs x hi/lo)
    float2* sEpi = (float2*)(dyn + 6*ABUF + 4*BBUF);   // [64][4]

    const int tid  = threadIdx.x;
    const int lane = tid & 31;
    const int warp = tid >> 5;
    const int mw = warp >> 2, nw = warp & 3;
    const int g = lane >> 2, tig = lane & 3;
    const int mbase = blockIdx.x * 64;

    float acc[16][4];
    #pragma unroll
    for (int nt = 0; nt < 16; nt++)
        #pragma unroll
        for (int c = 0; c < 4; c++) acc[nt][c] = 0.f;

    float kxA = 0.f; float2 wxA = make_float2(1.f, 0.f);
    if (tid < 64){
        kxA = ktraj[mbase + tid];
        float s, c; sincosf(kxA, &s, &c);
        wxA = make_float2(c, -s);              // e^{-i kx}
    }

    // ---- helpers (inline) ----
    // A-gen for step sg into buffer ab
    #define GEN_A(ab, sg) do{ \
        if (tid < 64){ \
            float ang = kxA * (float)(128 - (sg)*8); \
            float2 cur; sincosf(ang, &cur.y, &cur.x); \
            u32* ah_ = sA + (ab)*2*ABUF; u32* al_ = ah_ + ABUF; \
            _Pragma("unroll") \
            for (int i_ = 0; i_ < 8; i_++){ \
                u32 h_, l_; csplit(cur.x, cur.y, h_, l_); \
                ah_[tid*AST + i_] = h_; al_[tid*AST + i_] = l_; \
                cur = cmulf(cur, wxA); \
            } \
        } \
    } while(0)

    #define COPY_B(bb, sg) do{ \
        u32* bh_ = sB + (bb)*2*BBUF; u32* bl_ = bh_ + BBUF; \
        int u0_ = (sg)*8; \
        _Pragma("unroll") \
        for (int p_ = 0; p_ < 2; p_++){ \
            int seg_ = tid + p_*512; \
            int r_ = seg_ >> 7, si_ = (seg_ & 127)*4; \
            cpa16(bh_ + r_*BST + si_, g_Bh + (u0_ + r_)*512 + si_); \
            cpa16(bl_ + r_*BST + si_, g_Bl + (u0_ + r_)*512 + si_); \
        } \
        CP_COMMIT(); \
    } while(0)

    // prologue
    COPY_B(0, 0);
    GEN_A(0, 0);

    for (int s = 0; s < 32; s++){
        if (s < 31) GEN_A((s+1)%3, s+1);
        __syncthreads();
        if (s < 31){ COPY_B((s+1)&1, s+1); CP_WAIT(1); }
        else        CP_WAIT(0);

        const u32* ah = sA + (s%3)*2*ABUF; const u32* al = ah + ABUF;
        const u32* bh = sB + (s&1)*2*BBUF; const u32* bl = bh + BBUF;

        const int m0 = mw*16;
        u32 ah0 = ah[(m0+g)*AST + tig],   ah1 = ah[(m0+g+8)*AST + tig];
        u32 ah2 = ah[(m0+g)*AST + tig+4], ah3 = ah[(m0+g+8)*AST + tig+4];
        u32 al0 = al[(m0+g)*AST + tig],   al1 = al[(m0+g+8)*AST + tig];
        u32 al2 = al[(m0+g)*AST + tig+4], al3 = al[(m0+g+8)*AST + tig+4];
        #pragma unroll
        for (int nt = 0; nt < 16; nt++){
            int col = nw*128 + nt*8 + g;
            u32 bh0 = bh[ tig   *BST + col], bh1 = bh[(tig+4)*BST + col];
            u32 bl0 = bl[ tig   *BST + col], bl1 = bl[(tig+4)*BST + col];
            MMA(acc[nt], ah0, ah1, ah2, ah3, bh0, bh1);
            MMA(acc[nt], ah0, ah1, ah2, ah3, bl0, bl1);
            MMA(acc[nt], al0, al1, al2, al3, bh0, bh1);
        }
    }

    // ---- Epilogue: A_m = ORTHO * sum_w C[m,w]*Ey[m,w], DC blend ----
    float lam = 1.f / (1.f + expf(-lambda_p[0]));

    #pragma unroll
    for (int r = 0; r < 2; r++){
        int ml = mw*16 + g + 8*r;
        int m  = mbase + ml;
        float ky = ktraj[M_TOTAL + m];
        int w0 = nw*64 + tig;
        float2 e, st;
        { float s_, c_; sincosf(-ky * (float)(w0 - 128), &s_, &c_); e  = make_float2(c_, s_); }
        { float s_, c_; sincosf(-4.f * ky,               &s_, &c_); st = make_float2(c_, s_); }
        float2 part = make_float2(0.f, 0.f);
        #pragma unroll
        for (int nt = 0; nt < 16; nt++){
            float cr = acc[nt][2*r], ci = acc[nt][2*r + 1];
            part.x += cr*e.x - ci*e.y;
            part.y += cr*e.y + ci*e.x;
            e = cmulf(e, st);
        }
        part.x += __shfl_xor_sync(0xffffffffu, part.x, 1);
        part.y += __shfl_xor_sync(0xffffffffu, part.y, 1);
        part.x += __shfl_xor_sync(0xffffffffu, part.x, 2);
        part.y += __shfl_xor_sync(0xffffffffu, part.y, 2);
        if (tig == 0) sEpi[ml*4 + nw] = part;
    }
    __syncthreads();

    if (tid < 64){
        float2 s0 = sEpi[tid*4 + 0];
        s0.x += sEpi[tid*4+1].x + sEpi[tid*4+2].x + sEpi[tid*4+3].x;
        s0.y += sEpi[tid*4+1].y + sEpi[tid*4+2].y + sEpi[tid*4+3].y;
        int m = mbase + tid;
        float kx = ktraj[m], ky = ktraj[M_TOTAL + m];
        float dcf = sqrtf(kx*kx + ky*ky);
        float ar = s0.x * ORTHO_F, ai = s0.y * ORTHO_F;
        int tt = m % 640, ss = m / 640;
        const float* yp = y_radial + ((size_t)tt*288 + ss)*2;
        float2 kd;
        kd.x = lam*dcf*ar + (1.f - lam)*yp[0];
        kd.y = lam*dcf*ai + (1.f - lam)*yp[1];
        g_kdc[m] = kd;
    }
    #undef GEN_A
    #undef COPY_B
}

// ============================================================================
// Adjoint: block 64 u x 512 n', split-K over 72 chunks x 4 u-blocks.
// Pipelined triple-buffer gen (all 512 threads generate), 1 sync/step.
// ============================================================================
#define ADJ_MS 2560
#define ADJ_STEPS (ADJ_MS/8)

__global__ __launch_bounds__(512, 1) void adj_kernel(
    const float* __restrict__ ktraj,
    float* __restrict__ out)
{
    extern __shared__ u32 dyn[];
    u32* sA = dyn;                 // 6*ABUF (3 bufs x hi/lo)
    u32* sB = dyn + 6*ABUF;        // 6*BBUF (3 bufs x hi/lo)

    const int tid  = threadIdx.x;
    const int lane = tid & 31;
    const int warp = tid >> 5;
    const int uw = warp >> 2, nw = warp & 3;
    const int g = lane >> 2, tig = lane & 3;
    const int ublk = blockIdx.y;
    const int m0base = blockIdx.x * ADJ_MS;

    float acc[16][4];
    #pragma unroll
    for (int nt = 0; nt < 16; nt++)
        #pragma unroll
        for (int c = 0; c < 4; c++) acc[nt][c] = 0.f;

    // gen roles: every thread does 1 A entry + 4 B entries
    const int bml = tid >> 6, bv0 = tid & 63;    // B: row bml, v = bv0+64i
    const int aml = tid & 7,  au  = tid >> 3;    // A: u row au, m-col aml
    const float u_c = (float)(ublk*64 + au - 128);

    float kx_p = ktraj[m0base + aml];
    float ky_p = ktraj[M_TOTAL + m0base + bml];
    float2 kd_p = g_kdc[m0base + bml];

    #define GEN_STEP(ab, sg) do{ \
        /* A: one entry */ \
        { float2 e_; sincosf(kx_p * u_c, &e_.y, &e_.x); \
          u32 h_, l_; csplit(e_.x, e_.y, h_, l_); \
          u32* ah_ = sA + (ab)*2*ABUF; \
          ah_[au*AST + aml] = h_; (ah_ + ABUF)[au*AST + aml] = l_; } \
        /* B: 4 entries, v strided by 64 */ \
        { float2 kd_ = make_float2(kd_p.x*ORTHO_F, kd_p.y*ORTHO_F); \
          float2 e_; sincosf(ky_p * (float)(bv0 - 128), &e_.y, &e_.x); \
          float2 bb_ = cmulf(kd_, e_); \
          float2 w64_; sincosf(ky_p * 64.f, &w64_.y, &w64_.x); \
          u32* bh_ = sB + (ab)*2*BBUF; u32* bl_ = bh_ + BBUF; \
          _Pragma("unroll") \
          for (int i_ = 0; i_ < 4; i_++){ \
            int v_ = bv0 + 64*i_; \
            u32 h_, l_; csplit(bb_.x, bb_.y, h_, l_); \
            u64 hv_ = (u64)(h_ ^ 0x80000000u) | ((u64)__byte_perm(h_, h_, 0x1032) << 32); \
            *(u64*)&bh_[bml*BST + 2*v_] = hv_; \
            u64 lv_ = (u64)(l_ ^ 0x80000000u) | ((u64)__byte_perm(l_, l_, 0x1032) << 32); \
            *(u64*)&bl_[bml*BST + 2*v_] = lv_; \
            bb_ = cmulf(bb_, w64_); \
          } } \
        /* prefetch next step params */ \
        if ((sg) + 1 < ADJ_STEPS){ \
            int mn_ = m0base + ((sg)+1)*8; \
            kx_p = ktraj[mn_ + aml]; \
            ky_p = ktraj[M_TOTAL + mn_ + bml]; \
            kd_p = g_kdc[mn_ + bml]; \
        } \
    } while(0)

    GEN_STEP(0, 0);

    for (int s = 0; s < ADJ_STEPS; s++){
        if (s + 1 < ADJ_STEPS) GEN_STEP((s+1)%3, s+1);
        __syncthreads();

        const u32* ah = sA + (s%3)*2*ABUF; const u32* al = ah + ABUF;
        const u32* bh = sB + (s%3)*2*BBUF; const u32* bl = bh + BBUF;

        const int u0 = uw*16;
        u32 ah0 = ah[(u0+g)*AST + tig],   ah1 = ah[(u0+g+8)*AST + tig];
        u32 ah2 = ah[(u0+g)*AST + tig+4], ah3 = ah[(u0+g+8)*AST + tig+4];
        u32 al0 = al[(u0+g)*AST + tig],   al1 = al[(u0+g+8)*AST + tig];
        u32 al2 = al[(u0+g)*AST + tig+4], al3 = al[(u0+g+8)*AST + tig+4];
        #pragma unroll
        for (int nt = 0; nt < 16; nt++){
            int col = nw*128 + nt*8 + g;
            u32 bh0 = bh[ tig   *BST + col], bh1 = bh[(tig+4)*BST + col];
            u32 bl0 = bl[ tig   *BST + col], bl1 = bl[(tig+4)*BST + col];
            MMA(acc[nt], ah0, ah1, ah2, ah3, bh0, bh1);
            MMA(acc[nt], ah0, ah1, ah2, ah3, bl0, bl1);
            MMA(acc[nt], al0, al1, al2, al3, bh0, bh1);
        }
    }
    #undef GEN_STEP

    // split-K accumulate
    #pragma unroll
    for (int nt = 0; nt < 16; nt++){
        int np = nw*128 + nt*8 + 2*tig;
        int r0 = ublk*64 + uw*16 + g;
        float* p0 = out + (size_t)r0*512 + np;
        float* p1 = out + (size_t)(r0+8)*512 + np;
        atomicAdd(p0,     acc[nt][0]);
        atomicAdd(p0 + 1, acc[nt][1]);
        atomicAdd(p1,     acc[nt][2]);
        atomicAdd(p1 + 1, acc[nt][3]);
    }
}

extern "C" void kernel_launch(void* const* d_in, const int* in_sizes, int n_in,
                              void* d_out, int out_size)
{
    const float* x   = (const float*)d_in[0];  // (1,1,256,256,2)
    const float* y   = (const float*)d_in[1];  // (640,288,2)
    const float* lp  = (const float*)d_in[2];  // (1,)
    const float* kt  = (const float*)d_in[3];  // (1,2,184320)
    float* out = (float*)d_out;                // (1,1,256,256,2)

    const int FWD_SMEM = (6*ABUF + 4*BBUF + 512) * 4;   // ~85 KB
    const int ADJ_SMEM = (6*ABUF + 6*BBUF) * 4;         // ~115 KB
    cudaFuncSetAttribute(fwd_kernel, cudaFuncAttributeMaxDynamicSharedMemorySize, FWD_SMEM);
    cudaFuncSetAttribute(adj_kernel, cudaFuncAttributeMaxDynamicSharedMemorySize, ADJ_SMEM);

    cudaMemsetAsync(d_out, 0, (size_t)out_size * sizeof(float), 0);
    prep_kernel<<<256, 256>>>(x);
    fwd_kernel<<<M_TOTAL/64, 512, FWD_SMEM>>>(y, lp, kt);
    adj_kernel<<<dim3(72, 4), 512, ADJ_SMEM>>>(kt, out);
}

// round 9
// speedup vs baseline: 2.8464x; 1.1012x over previous
#include <cuda_runtime.h>
#include <cuda_bf16.h>
#include <math.h>

#define M_TOTAL 184320
#define IMG 256
#define ORTHO_F (1.0f/256.0f)

typedef unsigned int u32;
typedef unsigned long long u64;

// ---- static device scratch ----
__device__ float2 g_kdc[M_TOTAL];          // fwd raw partial sums -> blended kdc
__device__ u32 g_Bh[256*512];              // expanded image bf16-hi, [u][n']
__device__ u32 g_Bl[256*512];              // bf16-lo residual

__device__ __forceinline__ float2 cmulf(float2 a, float2 b){
    return make_float2(fmaf(a.x,b.x,-(a.y*b.y)), fmaf(a.x,b.y,a.y*b.x));
}
__device__ __forceinline__ u32 bf2pack(float x, float y){
    u32 r; asm("cvt.rn.bf16x2.f32 %0, %1, %2;" : "=r"(r) : "f"(y), "f"(x)); return r;
}
__device__ __forceinline__ void csplit(float x, float y, u32 &h32, u32 &l32){
    h32 = bf2pack(x, y);
    float hx = __uint_as_float(h32 << 16);
    float hy = __uint_as_float(h32 & 0xFFFF0000u);
    l32 = bf2pack(x - hx, y - hy);
}

#define MMA(c, a0,a1,a2,a3, b0,b1) \
    asm volatile("mma.sync.aligned.m16n8k16.row.col.f32.bf16.bf16.f32 " \
        "{%0,%1,%2,%3}, {%4,%5,%6,%7}, {%8,%9}, {%0,%1,%2,%3};" \
        : "+f"((c)[0]), "+f"((c)[1]), "+f"((c)[2]), "+f"((c)[3]) \
        : "r"(a0), "r"(a1), "r"(a2), "r"(a3), "r"(b0), "r"(b1))

__device__ __forceinline__ u32 smem_u32(const void* p){
    u32 a; asm("{ .reg .u64 t; cvta.to.shared.u64 t, %1; cvt.u32.u64 %0, t; }" : "=r"(a) : "l"(p));
    return a;
}
__device__ __forceinline__ void cpa16(u32 smaddr, const void* src){
    asm volatile("cp.async.cg.shared.global [%0], [%1], 16;" :: "r"(smaddr), "l"(src));
}
__device__ __forceinline__ void cpa16p(u32* dst, const u32* src){
    u32 d = (u32)__cvta_generic_to_shared(dst);
    asm volatile("cp.async.cg.shared.global [%0], [%1], 16;" :: "r"(d), "l"(src));
}
#define CP_COMMIT() asm volatile("cp.async.commit_group;")
#define CP_WAIT(n)  asm volatile("cp.async.wait_group %0;" :: "n"(n) : "memory")

// ============================================================================
// Prep: expand fp32 image to split-bf16 real-GEMM B layout; zero g_kdc.
// Row u, col 2w = (r, -i), col 2w+1 = (i, r).
// ============================================================================
__global__ void prep_kernel(const float* __restrict__ img){
    int idx = blockIdx.x*256 + threadIdx.x;       // 65536
    float2 p = ((const float2*)img)[idx];
    int u = idx >> 8, w = idx & 255;
    u32 h32, l32; csplit(p.x, p.y, h32, l32);
    g_Bh[u*512 + 2*w    ] = h32 ^ 0x80000000u;
    g_Bh[u*512 + 2*w + 1] = __byte_perm(h32, h32, 0x1032);
    g_Bl[u*512 + 2*w    ] = l32 ^ 0x80000000u;
    g_Bl[u*512 + 2*w + 1] = __byte_perm(l32, l32, 0x1032);
    for (int i = idx; i < 2*M_TOTAL; i += 65536)
        ((float*)g_kdc)[i] = 0.f;
}

// ============================================================================
// Forward: raw sums -> g_kdc partials (atomic).
// Block: 128 m x 256 n' (nh = w-half), 256 thr = 8 warps (4 mw x 2 nw),
// warp tile 32m x 128n'. 32 K-steps of 16 k'.
// A gen: ONE thread per m-row (tid<128), R4-proven semantics (sincos seed at
// u0, x e^{-i kx} recurrence over the 8 k-pairs). Double-buffered, 1 sync/step.
// ============================================================================
// smem: A buf b at b*12288 (hi 6144 = 128 rows x 12 u32, lo +6144)
//       B buf b at 24576 + b*16896 (hi 8448 = 8 rows x 264 u32, lo +8448)
#define F_SMEM 58368

__global__ __launch_bounds__(256, 1) void fwd_kernel(
    const float* __restrict__ ktraj)
{
    extern __shared__ char smem[];
    const u32 sbase = smem_u32(smem);
    const int tid  = threadIdx.x;
    const int lane = tid & 31;
    const int warp = tid >> 5;
    const int mw = warp >> 1, nw = warp & 1;
    const int g = lane >> 2, tig = lane & 3;
    const int mbase = blockIdx.x * 128;
    const int nh = blockIdx.y;

    float acc[2][16][4];
    #pragma unroll
    for (int f = 0; f < 2; f++)
        #pragma unroll
        for (int nt = 0; nt < 16; nt++)
            #pragma unroll
            for (int c = 0; c < 4; c++) acc[f][nt][c] = 0.f;

    // A-gen: thread tid<128 owns m-row tid (R4-proven mapping)
    const float kxA = (tid < 128) ? ktraj[mbase + tid] : 0.f;
    float2 wxA; sincosf(-kxA, &wxA.y, &wxA.x);          // e^{-i kx}

    #define GEN_A(buf_, s_) do{ \
        if (tid < 128){ \
            char* ah_ = smem + (buf_)*12288; \
            float ang_ = kxA * (float)(128 - 8*(s_)); \
            float2 cur_; sincosf(ang_, &cur_.y, &cur_.x); \
            _Pragma("unroll") \
            for (int j_ = 0; j_ < 8; j_++){ \
                u32 h_, l_; csplit(cur_.x, cur_.y, h_, l_); \
                int off_ = (tid*12 + j_)*4; \
                *(u32*)(ah_ + off_)        = h_; \
                *(u32*)(ah_ + 6144 + off_) = l_; \
                cur_ = cmulf(cur_, wxA); \
            } \
        } \
    }while(0)

    #define COPY_B(buf_, s_) do{ \
        u32 bb_ = sbase + 24576 + (buf_)*16896; \
        _Pragma("unroll") \
        for (int q_ = 0; q_ < 2; q_++){ \
            int idx_ = tid + q_*256; \
            int r_ = idx_ >> 6, c16_ = idx_ & 63; \
            const u32* sh_ = g_Bh + (8*(s_) + r_)*512 + nh*256 + c16_*4; \
            const u32* sl_ = g_Bl + (8*(s_) + r_)*512 + nh*256 + c16_*4; \
            cpa16(bb_ + r_*1056 + c16_*16,        sh_); \
            cpa16(bb_ + 8448 + r_*1056 + c16_*16, sl_); \
        } \
        CP_COMMIT(); \
    }while(0)

    COPY_B(0, 0);
    GEN_A(0, 0);

    for (int s = 0; s < 32; s++){
        __syncthreads();
        if (s < 31){ COPY_B((s+1)&1, s+1); GEN_A((s+1)&1, s+1); CP_WAIT(1); }
        else CP_WAIT(0);

        const char* ab = smem + (s&1)*12288;
        const char* bb = smem + 24576 + (s&1)*16896;

        u32 a[2][8];
        #pragma unroll
        for (int f = 0; f < 2; f++){
            int r0 = mw*32 + f*16 + g;
            a[f][0] = *(const u32*)(ab + ( r0   *12 + tig  )*4);
            a[f][1] = *(const u32*)(ab + ((r0+8)*12 + tig  )*4);
            a[f][2] = *(const u32*)(ab + ( r0   *12 + tig+4)*4);
            a[f][3] = *(const u32*)(ab + ((r0+8)*12 + tig+4)*4);
            a[f][4] = *(const u32*)(ab + 6144 + ( r0   *12 + tig  )*4);
            a[f][5] = *(const u32*)(ab + 6144 + ((r0+8)*12 + tig  )*4);
            a[f][6] = *(const u32*)(ab + 6144 + ( r0   *12 + tig+4)*4);
            a[f][7] = *(const u32*)(ab + 6144 + ((r0+8)*12 + tig+4)*4);
        }
        #pragma unroll
        for (int nt = 0; nt < 16; nt++){
            int col = nw*128 + nt*8 + g;
            u32 bh0 = *(const u32*)(bb + ( tig   *264 + col)*4);
            u32 bh1 = *(const u32*)(bb + ((tig+4)*264 + col)*4);
            u32 bl0 = *(const u32*)(bb + 8448 + ( tig   *264 + col)*4);
            u32 bl1 = *(const u32*)(bb + 8448 + ((tig+4)*264 + col)*4);
            #pragma unroll
            for (int f = 0; f < 2; f++){
                MMA(acc[f][nt], a[f][0], a[f][1], a[f][2], a[f][3], bh0, bh1);
                MMA(acc[f][nt], a[f][0], a[f][1], a[f][2], a[f][3], bl0, bl1);
                MMA(acc[f][nt], a[f][4], a[f][5], a[f][6], a[f][7], bh0, bh1);
            }
        }
    }
    #undef GEN_A
    #undef COPY_B

    // ---- Epilogue: partial raw sum_w C[m,w] Ey[m,w] -> atomic g_kdc ----
    #pragma unroll
    for (int f = 0; f < 2; f++){
        #pragma unroll
        for (int r = 0; r < 2; r++){
            int ml = mw*32 + f*16 + g + 8*r;
            int m  = mbase + ml;
            float ky = ktraj[M_TOTAL + m];
            int w0 = nh*128 + nw*64 + tig;
            float2 e, st;
            { float s_, c_; sincosf(-ky * (float)(w0 - 128), &s_, &c_); e  = make_float2(c_, s_); }
            { float s_, c_; sincosf(-4.f * ky,               &s_, &c_); st = make_float2(c_, s_); }
            float2 part = make_float2(0.f, 0.f);
            #pragma unroll
            for (int nt = 0; nt < 16; nt++){
                float cr = acc[f][nt][2*r], ci = acc[f][nt][2*r + 1];
                part.x += cr*e.x - ci*e.y;
                part.y += cr*e.y + ci*e.x;
                e = cmulf(e, st);
            }
            part.x += __shfl_xor_sync(0xffffffffu, part.x, 1);
            part.y += __shfl_xor_sync(0xffffffffu, part.y, 1);
            part.x += __shfl_xor_sync(0xffffffffu, part.x, 2);
            part.y += __shfl_xor_sync(0xffffffffu, part.y, 2);
            if (tig == 0){
                atomicAdd(&g_kdc[m].x, part.x);
                atomicAdd(&g_kdc[m].y, part.y);
            }
        }
    }
}

// ============================================================================
// Blend: g_kdc raw sums -> kdc = lam*dcf*(ORTHO*sum) + (1-lam)*y
// ============================================================================
__global__ void blend_kernel(
    const float* __restrict__ y_radial,
    const float* __restrict__ lambda_p,
    const float* __restrict__ ktraj)
{
    int m = blockIdx.x*256 + threadIdx.x;
    if (m >= M_TOTAL) return;
    float lam = 1.f / (1.f + expf(-lambda_p[0]));
    float kx = ktraj[m], ky = ktraj[M_TOTAL + m];
    float dcf = sqrtf(kx*kx + ky*ky);
    float2 s = g_kdc[m];
    float ar = s.x * ORTHO_F, ai = s.y * ORTHO_F;
    int tt = m % 640, ss = m / 640;
    const float* yp = y_radial + ((size_t)tt*288 + ss)*2;
    float2 kd;
    kd.x = lam*dcf*ar + (1.f - lam)*yp[0];
    kd.y = lam*dcf*ai + (1.f - lam)*yp[1];
    g_kdc[m] = kd;
}

// ============================================================================
// Adjoint: R4's PROVEN bf16-MMA adjoint, verbatim.
// Block 64 u x 512 n', split-K 72 chunks x 4 ublk. 512 threads (16 warps =
// 4 uw x 4 nw). Steps of 8 m, triple-buffered gen, 1 sync/step.
// ============================================================================
#define AST 12
#define BST 520
#define ABUF (64*AST)
#define BBUF (8*BST)
#define ADJ_MS 2560
#define ADJ_STEPS (ADJ_MS/8)
#define A_SMEM ((6*ABUF + 6*BBUF) * 4)

__global__ __launch_bounds__(512, 1) void adj_kernel(
    const float* __restrict__ ktraj,
    float* __restrict__ out)
{
    extern __shared__ u32 dyn[];
    u32* sA = dyn;                 // 6*ABUF (3 bufs x hi/lo)
    u32* sB = dyn + 6*ABUF;        // 6*BBUF (3 bufs x hi/lo)

    const int tid  = threadIdx.x;
    const int lane = tid & 31;
    const int warp = tid >> 5;
    const int uw = warp >> 2, nw = warp & 3;
    const int g = lane >> 2, tig = lane & 3;
    const int ublk = blockIdx.y;
    const int m0base = blockIdx.x * ADJ_MS;

    float acc[16][4];
    #pragma unroll
    for (int nt = 0; nt < 16; nt++)
        #pragma unroll
        for (int c = 0; c < 4; c++) acc[nt][c] = 0.f;

    // gen roles: every thread does 1 A entry + 4 B entries
    const int bml = tid >> 6, bv0 = tid & 63;    // B: row bml, v = bv0+64i
    const int aml = tid & 7,  au  = tid >> 3;    // A: u row au, m-col aml
    const float u_c = (float)(ublk*64 + au - 128);

    float kx_p = ktraj[m0base + aml];
    float ky_p = ktraj[M_TOTAL + m0base + bml];
    float2 kd_p = g_kdc[m0base + bml];

    #define GEN_STEP(ab, sg) do{ \
        /* A: one entry */ \
        { float2 e_; sincosf(kx_p * u_c, &e_.y, &e_.x); \
          u32 h_, l_; csplit(e_.x, e_.y, h_, l_); \
          u32* ah_ = sA + (ab)*2*ABUF; \
          ah_[au*AST + aml] = h_; (ah_ + ABUF)[au*AST + aml] = l_; } \
        /* B: 4 entries, v strided by 64 */ \
        { float2 kd_ = make_float2(kd_p.x*ORTHO_F, kd_p.y*ORTHO_F); \
          float2 e_; sincosf(ky_p * (float)(bv0 - 128), &e_.y, &e_.x); \
          float2 bb_ = cmulf(kd_, e_); \
          float2 w64_; sincosf(ky_p * 64.f, &w64_.y, &w64_.x); \
          u32* bh_ = sB + (ab)*2*BBUF; u32* bl_ = bh_ + BBUF; \
          _Pragma("unroll") \
          for (int i_ = 0; i_ < 4; i_++){ \
            int v_ = bv0 + 64*i_; \
            u32 h_, l_; csplit(bb_.x, bb_.y, h_, l_); \
            u64 hv_ = (u64)(h_ ^ 0x80000000u) | ((u64)__byte_perm(h_, h_, 0x1032) << 32); \
            *(u64*)&bh_[bml*BST + 2*v_] = hv_; \
            u64 lv_ = (u64)(l_ ^ 0x80000000u) | ((u64)__byte_perm(l_, l_, 0x1032) << 32); \
            *(u64*)&bl_[bml*BST + 2*v_] = lv_; \
            bb_ = cmulf(bb_, w64_); \
          } } \
        /* prefetch next step params */ \
        if ((sg) + 1 < ADJ_STEPS){ \
            int mn_ = m0base + ((sg)+1)*8; \
            kx_p = ktraj[mn_ + aml]; \
            ky_p = ktraj[M_TOTAL + mn_ + bml]; \
            kd_p = g_kdc[mn_ + bml]; \
        } \
    } while(0)

    GEN_STEP(0, 0);

    for (int s = 0; s < ADJ_STEPS; s++){
        if (s + 1 < ADJ_STEPS) GEN_STEP((s+1)%3, s+1);
        __syncthreads();

        const u32* ah = sA + (s%3)*2*ABUF; const u32* al = ah + ABUF;
        const u32* bh = sB + (s%3)*2*BBUF; const u32* bl = bh + BBUF;

        const int u0 = uw*16;
        u32 ah0 = ah[(u0+g)*AST + tig],   ah1 = ah[(u0+g+8)*AST + tig];
        u32 ah2 = ah[(u0+g)*AST + tig+4], ah3 = ah[(u0+g+8)*AST + tig+4];
        u32 al0 = al[(u0+g)*AST + tig],   al1 = al[(u0+g+8)*AST + tig];
        u32 al2 = al[(u0+g)*AST + tig+4], al3 = al[(u0+g+8)*AST + tig+4];
        #pragma unroll
        for (int nt = 0; nt < 16; nt++){
            int col = nw*128 + nt*8 + g;
            u32 bh0 = bh[ tig   *BST + col], bh1 = bh[(tig+4)*BST + col];
            u32 bl0 = bl[ tig   *BST + col], bl1 = bl[(tig+4)*BST + col];
            MMA(acc[nt], ah0, ah1, ah2, ah3, bh0, bh1);
            MMA(acc[nt], ah0, ah1, ah2, ah3, bl0, bl1);
            MMA(acc[nt], al0, al1, al2, al3, bh0, bh1);
        }
    }
    #undef GEN_STEP

    // split-K accumulate
    #pragma unroll
    for (int nt = 0; nt < 16; nt++){
        int np = nw*128 + nt*8 + 2*tig;
        int r0 = ublk*64 + uw*16 + g;
        float* p0 = out + (size_t)r0*512 + np;
        float* p1 = out + (size_t)(r0+8)*512 + np;
        atomicAdd(p0,     acc[nt][0]);
        atomicAdd(p0 + 1, acc[nt][1]);
        atomicAdd(p1,     acc[nt][2]);
        atomicAdd(p1 + 1, acc[nt][3]);
    }
}

extern "C" void kernel_launch(void* const* d_in, const int* in_sizes, int n_in,
                              void* d_out, int out_size)
{
    const float* x   = (const float*)d_in[0];  // (1,1,256,256,2)
    const float* y   = (const float*)d_in[1];  // (640,288,2)
    const float* lp  = (const float*)d_in[2];  // (1,)
    const float* kt  = (const float*)d_in[3];  // (1,2,184320)
    float* out = (float*)d_out;                // (1,1,256,256,2)

    cudaFuncSetAttribute(fwd_kernel, cudaFuncAttributeMaxDynamicSharedMemorySize, F_SMEM);
    cudaFuncSetAttribute(adj_kernel, cudaFuncAttributeMaxDynamicSharedMemorySize, A_SMEM);

    cudaMemsetAsync(d_out, 0, (size_t)out_size * sizeof(float), 0);
    prep_kernel<<<256, 256>>>(x);
    fwd_kernel<<<dim3(M_TOTAL/128, 2), 256, F_SMEM>>>(kt);
    blend_kernel<<<(M_TOTAL + 255)/256, 256>>>(y, lp, kt);
    adj_kernel<<<dim3(72, 4), 512, A_SMEM>>>(kt, out);
}